// round 12
// baseline (speedup 1.0000x reference)
#include <cuda_runtime.h>
#include <cuda_fp16.h>
#include <cstdint>

// PolyConv: CSR build + atomic-free fused iterations, 4-lane node groups,
// natural order. fp32 state in PLANE-MAJOR layout (halved state wavefronts);
// gather fp32 (iter1) then fp16 row-major mirrors (iters 2-4).
// Inputs: feat [N*32 f32], src [E i32], dst [E i32], mask [E f32]
// Output: h [N*32 f32]

#define N_NODES 100000
#define N_EDGES 1600000
#define DFEAT   32
#define DV4     (DFEAT / 4)        // 8 float4 per node row
#define NV4     (N_NODES * DV4)
#define NH4     (N_NODES * 4)      // 4 uint4 (8 halves) per node row

#define SCAN_B  1024
#define N_SBLK  ((N_NODES + SCAN_B - 1) / SCAN_B)   // 98

// ---- scratch (static __device__, no allocation) ----
__device__ int    g_cnt[N_NODES];
__device__ float  g_degf[N_NODES];
__device__ int    g_row[N_NODES + 1];
__device__ int    g_cursor[N_NODES];
__device__ int    g_bsum[N_SBLK];
__device__ float2 g_fac[N_NODES];        // {dinv^2, sqrt(max(deg,1))}
__device__ int2   g_edges[N_EDGES];      // CSR: {src, mask_bits} grouped by dst
__device__ float4 g_src32[NV4];          // fp32 gather source for iter1 (row-major)
__device__ float4 g_sT[NV4];             // fp32 state, PLANE-MAJOR: [p*N + n], p=0..7
__device__ uint4  g_halfA[NH4];          // fp16 gather mirror (ping, row-major)
__device__ uint4  g_halfB[NH4];          // fp16 gather mirror (pong, row-major)

static __device__ __forceinline__ unsigned h2u(__half2 h) {
    return *reinterpret_cast<unsigned*>(&h);
}

// ---------------------------------------------------------------------------
__global__ void k_zero() {
    int i = blockIdx.x * blockDim.x + threadIdx.x;
    if (i < N_NODES) { g_cnt[i] = 0; g_degf[i] = 0.0f; }
}

// histogram: edge count + mask-sum per dst
__global__ void k_hist(const int* __restrict__ dst, const float* __restrict__ mask, int E) {
    int e = blockIdx.x * blockDim.x + threadIdx.x;
    if (e < E) {
        int d = dst[e];
        atomicAdd(&g_cnt[d], 1);
        atomicAdd(&g_degf[d], mask[e]);
    }
}

// scan stage 1: shuffle-based per-block exclusive scan of g_cnt -> g_row.
__global__ void k_scan1() {
    __shared__ int warp_sums[32];
    int t = threadIdx.x;
    int lane = t & 31, warp = t >> 5;
    int gid = blockIdx.x * SCAN_B + t;
    int v = (gid < N_NODES) ? g_cnt[gid] : 0;

    int x = v;
    #pragma unroll
    for (int o = 1; o < 32; o <<= 1) {
        int y = __shfl_up_sync(0xFFFFFFFFu, x, o);
        if (lane >= o) x += y;
    }
    if (lane == 31) warp_sums[warp] = x;
    __syncthreads();
    if (warp == 0) {
        int s = warp_sums[lane];
        #pragma unroll
        for (int o = 1; o < 32; o <<= 1) {
            int y = __shfl_up_sync(0xFFFFFFFFu, s, o);
            if (lane >= o) s += y;
        }
        warp_sums[lane] = s;
    }
    __syncthreads();
    int warp_off = (warp > 0) ? warp_sums[warp - 1] : 0;
    int incl = x + warp_off;
    if (gid < N_NODES) g_row[gid] = incl - v;
    if (t == SCAN_B - 1) g_bsum[blockIdx.x] = incl;
}

// stage 2+3: warp-reduce prior block totals, apply offset, init cursor,
// compute node factors from degf.
__global__ void k_scan23(int E) {
    __shared__ int s_prefix;
    int t = threadIdx.x;
    int nblk = blockIdx.x >> 2;           // owning 1024-wide scan block
    if (t < 32) {
        int sum = 0;
        for (int b = t; b < nblk; b += 32) sum += g_bsum[b];
        #pragma unroll
        for (int o = 16; o; o >>= 1) sum += __shfl_xor_sync(0xFFFFFFFFu, sum, o);
        if (t == 0) s_prefix = sum;
    }
    __syncthreads();
    int prefix = s_prefix;

    int gid = blockIdx.x * 256 + t;
    if (gid < N_NODES) {
        int r = g_row[gid] + prefix;
        g_row[gid] = r;
        g_cursor[gid] = r;
        float deg = fmaxf(g_degf[gid], 1.0f);
        float dinv = rsqrtf(deg);
        g_fac[gid] = make_float2(dinv * dinv, deg * dinv);  // {dinv^2, sqrt(deg)}
    }
    if (gid == 0) g_row[N_NODES] = E;
}

__global__ void k_scatter(const int* __restrict__ src, const int* __restrict__ dst,
                          const float* __restrict__ mask, int E) {
    int e = blockIdx.x * blockDim.x + threadIdx.x;
    if (e >= E) return;
    int d = dst[e];
    int pos = atomicAdd(&g_cursor[d], 1);
    g_edges[pos] = make_int2(src[e], __float_as_int(mask[e]));
}

// slim init: src32 = feat * dinv (4-lane groups, row-major, coalesced)
__global__ void __launch_bounds__(256)
k_init(const float4* __restrict__ feat4) {
    int t = threadIdx.x;
    int n = blockIdx.x * 64 + (t >> 2);
    if (n >= N_NODES) return;
    int c = t & 3;
    float dinv2rsq_dinv = 0.0f;  // placeholder
    (void)dinv2rsq_dinv;
    float2 fac = g_fac[n];
    // dinv = dinv2 * rsq  (dinv^2 * sqrt(deg) = deg^{-1} * deg^{1/2} = deg^{-1/2})
    float dinv = fac.x * fac.y;

    int i0 = n * DV4 + c * 2;
    float4 f0 = feat4[i0], f1 = feat4[i0 + 1];
    float4 s0, s1;
    s0.x = f0.x * dinv; s0.y = f0.y * dinv; s0.z = f0.z * dinv; s0.w = f0.w * dinv;
    s1.x = f1.x * dinv; s1.y = f1.y * dinv; s1.z = f1.z * dinv; s1.w = f1.w * dinv;
    g_src32[i0] = s0;
    g_src32[i0 + 1] = s1;
}

// iteration 1: fp32 gather from src32 (row-major); state write PLANE-MAJOR;
// mirror write row-major; h pure write.
__global__ void __launch_bounds__(256)
k_iter1(float4* __restrict__ h4, float theta0, float theta1) {
    int t = threadIdx.x;
    int n = blockIdx.x * 64 + (t >> 2);
    if (n >= N_NODES) return;
    int c = t & 3;

    int base = g_row[n];
    int end  = g_row[n + 1];
    float2 fac = g_fac[n];                       // 1 line per warp (consecutive n)

    int i0 = n * DV4 + c * 2;
    float4 o0 = g_src32[i0], o1 = g_src32[i0 + 1];

    float a0=0.f,a1=0.f,a2=0.f,a3=0.f,a4=0.f,a5=0.f,a6=0.f,a7=0.f;
    #pragma unroll 4
    for (int j = base; j < end; ++j) {
        int2 ed = g_edges[j];
        float m = __int_as_float(ed.y);
        const float4* p = &g_src32[ed.x * DV4 + c * 2];
        float4 v0 = p[0], v1 = p[1];
        a0 += v0.x * m; a1 += v0.y * m; a2 += v0.z * m; a3 += v0.w * m;
        a4 += v1.x * m; a5 += v1.y * m; a6 += v1.z * m; a7 += v1.w * m;
    }

    float dinv2 = fac.x, rsq = fac.y;
    float4 s0, s1;
    s0.x = o0.x - a0 * dinv2; s0.y = o0.y - a1 * dinv2;
    s0.z = o0.z - a2 * dinv2; s0.w = o0.w - a3 * dinv2;
    s1.x = o1.x - a4 * dinv2; s1.y = o1.y - a5 * dinv2;
    s1.z = o1.z - a6 * dinv2; s1.w = o1.w - a7 * dinv2;
    // plane-major state write: planes 2c and 2c+1, node n
    g_sT[(2 * c) * N_NODES + n]     = s0;
    g_sT[(2 * c + 1) * N_NODES + n] = s1;

    float tpr = theta0 * rsq, tr = theta1 * rsq;
    float4 h0, h1;
    h0.x = tpr * o0.x + tr * s0.x; h0.y = tpr * o0.y + tr * s0.y;
    h0.z = tpr * o0.z + tr * s0.z; h0.w = tpr * o0.w + tr * s0.w;
    h1.x = tpr * o1.x + tr * s1.x; h1.y = tpr * o1.y + tr * s1.y;
    h1.z = tpr * o1.z + tr * s1.z; h1.w = tpr * o1.w + tr * s1.w;
    h4[i0] = h0;
    h4[i0 + 1] = h1;

    uint4 hp;
    hp.x = h2u(__floats2half2_rn(s0.x, s0.y));
    hp.y = h2u(__floats2half2_rn(s0.z, s0.w));
    hp.z = h2u(__floats2half2_rn(s1.x, s1.y));
    hp.w = h2u(__floats2half2_rn(s1.z, s1.w));
    g_halfB[n * 4 + c] = hp;
}

// iterations 2-4: fp16 gather; plane-major state RMW; h RMW.
// sel: 1 -> in=halfA out=halfB, 0 -> in=halfB out=halfA.
__global__ void __launch_bounds__(256)
k_iter(float4* __restrict__ h4, float theta, int write_next, int sel) {
    const uint4* __restrict__ gin  = sel ? g_halfA : g_halfB;
    uint4* __restrict__       gout = sel ? g_halfB : g_halfA;

    int t = threadIdx.x;
    int n = blockIdx.x * 64 + (t >> 2);
    if (n >= N_NODES) return;
    int c = t & 3;

    int base = g_row[n];
    int end  = g_row[n + 1];
    float2 fac = g_fac[n];

    // hoisted plane-major state loads (4 contiguous lines per warp-instruction)
    int ip0 = (2 * c) * N_NODES + n;
    int ip1 = (2 * c + 1) * N_NODES + n;
    float4 s0 = g_sT[ip0], s1 = g_sT[ip1];

    float a0=0.f,a1=0.f,a2=0.f,a3=0.f,a4=0.f,a5=0.f,a6=0.f,a7=0.f;
    #pragma unroll 4
    for (int j = base; j < end; ++j) {
        int2 ed = g_edges[j];
        float m = __int_as_float(ed.y);
        uint4 v = gin[ed.x * 4 + c];
        float2 f;
        f = __half22float2(*reinterpret_cast<__half2*>(&v.x)); a0 += f.x*m; a1 += f.y*m;
        f = __half22float2(*reinterpret_cast<__half2*>(&v.y)); a2 += f.x*m; a3 += f.y*m;
        f = __half22float2(*reinterpret_cast<__half2*>(&v.z)); a4 += f.x*m; a5 += f.y*m;
        f = __half22float2(*reinterpret_cast<__half2*>(&v.w)); a6 += f.x*m; a7 += f.y*m;
    }

    float dinv2 = fac.x, rsq = fac.y;
    s0.x -= a0 * dinv2; s0.y -= a1 * dinv2; s0.z -= a2 * dinv2; s0.w -= a3 * dinv2;
    s1.x -= a4 * dinv2; s1.y -= a5 * dinv2; s1.z -= a6 * dinv2; s1.w -= a7 * dinv2;
    g_sT[ip0] = s0;
    g_sT[ip1] = s1;

    int i0 = n * DV4 + c * 2;
    float tr = theta * rsq;
    float4 h0 = h4[i0], h1 = h4[i0 + 1];
    h0.x += tr * s0.x; h0.y += tr * s0.y; h0.z += tr * s0.z; h0.w += tr * s0.w;
    h1.x += tr * s1.x; h1.y += tr * s1.y; h1.z += tr * s1.z; h1.w += tr * s1.w;
    h4[i0] = h0;
    h4[i0 + 1] = h1;

    if (write_next) {
        uint4 hp;
        hp.x = h2u(__floats2half2_rn(s0.x, s0.y));
        hp.y = h2u(__floats2half2_rn(s0.z, s0.w));
        hp.z = h2u(__floats2half2_rn(s1.x, s1.y));
        hp.w = h2u(__floats2half2_rn(s1.z, s1.w));
        gout[n * 4 + c] = hp;
    }
}

extern "C" void kernel_launch(void* const* d_in, const int* in_sizes, int n_in,
                              void* d_out, int out_size) {
    const float* feat = (const float*)d_in[0];
    const int*   src  = (const int*)d_in[1];
    const int*   dst  = (const int*)d_in[2];
    const float* mask = (const float*)d_in[3];
    float* out = (float*)d_out;

    const int E = in_sizes[1];
    const int TB = 256;

    // --- CSR build ---
    k_zero<<<(N_NODES + TB - 1) / TB, TB>>>();
    k_hist<<<(E + TB - 1) / TB, TB>>>(dst, mask, E);
    k_scan1<<<N_SBLK, SCAN_B>>>();
    k_scan23<<<(N_NODES + 255) / 256, 256>>>(E);
    k_scatter<<<(E + TB - 1) / TB, TB>>>(src, dst, mask, E);

    // --- init ---
    int node4_blocks = (N_NODES + 63) / 64;
    k_init<<<node4_blocks, TB>>>((const float4*)feat);

    // --- 4 fused iterations ---  theta = {0.2, -0.4, 0.3, -0.15, 0.05}
    k_iter1<<<node4_blocks, TB>>>((float4*)out, 0.2f, -0.4f);
    k_iter<<<node4_blocks, TB>>>((float4*)out, 0.3f,   1, 0);  // reads B, writes A
    k_iter<<<node4_blocks, TB>>>((float4*)out, -0.15f, 1, 1);  // reads A, writes B
    k_iter<<<node4_blocks, TB>>>((float4*)out, 0.05f,  0, 0);  // reads B
}

// round 13
// speedup vs baseline: 1.1521x; 1.1521x over previous
#include <cuda_runtime.h>
#include <cuda_fp16.h>
#include <cstdint>

// PolyConv: CSR build via warp-aggregated atomic row allocation (no scan
// kernels) + atomic-free fused iterations, 4-lane node groups, natural order.
// State fp32 in-place (row-major); gather fp32 (iter1) then fp16 ping-pong.
// Inputs: feat [N*32 f32], src [E i32], dst [E i32], mask [E f32]
// Output: h [N*32 f32]

#define N_NODES 100000
#define N_EDGES 1600000
#define DFEAT   32
#define DV4     (DFEAT / 4)        // 8 float4 per node row
#define NV4     (N_NODES * DV4)
#define NH4     (N_NODES * 4)      // 4 uint4 (8 halves) per node row

// ---- scratch (static __device__, zero-initialized; every call restores zeros) ----
__device__ int    g_cnt[N_NODES];        // in-degree; re-zeroed in iter4 tail
__device__ int    g_total;               // row allocator; re-zeroed in iter4 tail
__device__ int2   g_rows[N_NODES];       // {base, end} of node's CSR segment
__device__ int    g_cursor[N_NODES];
__device__ float2 g_fac[N_NODES];        // {dinv^2, sqrt(max(deg,1))}
__device__ int2   g_edges[N_EDGES];      // CSR: {src, mask_bits} grouped by dst
__device__ float4 g_src32[NV4];          // fp32 gather source for iter1 (T0 scaled)
__device__ float4 g_scaled[NV4];         // fp32 state, in-place (row-major)
__device__ uint4  g_halfA[NH4];          // fp16 gather mirror (ping)
__device__ uint4  g_halfB[NH4];          // fp16 gather mirror (pong)

static __device__ __forceinline__ unsigned h2u(__half2 h) {
    return *reinterpret_cast<unsigned*>(&h);
}

// ---------------------------------------------------------------------------
// histogram: edge count per dst (g_cnt starts zero: invariant)
__global__ void k_hist(const int* __restrict__ dst, int E) {
    int e = blockIdx.x * blockDim.x + threadIdx.x;
    if (e < E) atomicAdd(&g_cnt[dst[e]], 1);
}

// row allocation: warp-aggregated atomic segment assignment (order-free CSR).
__global__ void k_rows() {
    int n = blockIdx.x * blockDim.x + threadIdx.x;
    int lane = threadIdx.x & 31;
    int cnt = (n < N_NODES) ? g_cnt[n] : 0;

    // warp-inclusive scan of cnt
    int incl = cnt;
    #pragma unroll
    for (int o = 1; o < 32; o <<= 1) {
        int y = __shfl_up_sync(0xFFFFFFFFu, incl, o);
        if (lane >= o) incl += y;
    }
    int warp_base = 0;
    if (lane == 31) warp_base = atomicAdd(&g_total, incl);   // incl == warp total
    warp_base = __shfl_sync(0xFFFFFFFFu, warp_base, 31);

    if (n < N_NODES) {
        int base = warp_base + incl - cnt;
        g_rows[n] = make_int2(base, base + cnt);
        g_cursor[n] = base;
    }
}

__global__ void k_scatter(const int* __restrict__ src, const int* __restrict__ dst,
                          const float* __restrict__ mask, int E) {
    int e = blockIdx.x * blockDim.x + threadIdx.x;
    if (e >= E) return;
    int d = dst[e];
    int pos = atomicAdd(&g_cursor[d], 1);
    g_edges[pos] = make_int2(src[e], __float_as_int(mask[e]));
}

// fused fac + init: 4 lanes per node; mask-sum over CSR row (shuffle-reduce),
// write factors and src32 = feat*dinv.
__global__ void __launch_bounds__(256)
k_facinit(const float4* __restrict__ feat4) {
    int t = threadIdx.x;
    int n = blockIdx.x * 64 + (t >> 2);
    if (n >= N_NODES) return;     // whole warps exit together (8 nodes/warp)
    int c = t & 3;

    int2 rr = g_rows[n];
    float deg = 0.0f;
    for (int j = rr.x + c; j < rr.y; j += 4)
        deg += __int_as_float(g_edges[j].y);
    deg += __shfl_xor_sync(0xFFFFFFFFu, deg, 1);
    deg += __shfl_xor_sync(0xFFFFFFFFu, deg, 2);

    deg = fmaxf(deg, 1.0f);
    float dinv = rsqrtf(deg);
    if (c == 0) g_fac[n] = make_float2(dinv * dinv, deg * dinv); // {dinv^2, sqrt(deg)}

    int i0 = n * DV4 + c * 2;
    float4 f0 = feat4[i0], f1 = feat4[i0 + 1];
    float4 s0, s1;
    s0.x = f0.x * dinv; s0.y = f0.y * dinv; s0.z = f0.z * dinv; s0.w = f0.w * dinv;
    s1.x = f1.x * dinv; s1.y = f1.y * dinv; s1.z = f1.z * dinv; s1.w = f1.w * dinv;
    g_src32[i0] = s0;
    g_src32[i0 + 1] = s1;
}

// iteration 1: fp32 gather from src32; h pure write; writes fp32 state + fp16 mirror.
__global__ void __launch_bounds__(256)
k_iter1(float4* __restrict__ h4, float theta0, float theta1) {
    int t = threadIdx.x;
    int n = blockIdx.x * 64 + (t >> 2);
    if (n >= N_NODES) return;
    int c = t & 3;

    int2 rr = g_rows[n];

    float a0 = 0.f, a1 = 0.f, a2 = 0.f, a3 = 0.f;
    float a4 = 0.f, a5 = 0.f, a6 = 0.f, a7 = 0.f;

    #pragma unroll 2
    for (int j = rr.x; j < rr.y; ++j) {
        int2 ed = g_edges[j];
        float m = __int_as_float(ed.y);
        const float4* p = &g_src32[ed.x * DV4 + c * 2];
        float4 v0 = p[0], v1 = p[1];
        a0 += v0.x * m; a1 += v0.y * m; a2 += v0.z * m; a3 += v0.w * m;
        a4 += v1.x * m; a5 += v1.y * m; a6 += v1.z * m; a7 += v1.w * m;
    }

    float2 fac = g_fac[n];
    float dinv2 = fac.x, rsq = fac.y;

    int i0 = n * DV4 + c * 2;
    float4 o0 = g_src32[i0], o1 = g_src32[i0 + 1];
    float4 s0, s1;
    s0.x = o0.x - a0 * dinv2; s0.y = o0.y - a1 * dinv2;
    s0.z = o0.z - a2 * dinv2; s0.w = o0.w - a3 * dinv2;
    s1.x = o1.x - a4 * dinv2; s1.y = o1.y - a5 * dinv2;
    s1.z = o1.z - a6 * dinv2; s1.w = o1.w - a7 * dinv2;
    g_scaled[i0] = s0;
    g_scaled[i0 + 1] = s1;

    float tpr = theta0 * rsq, tr = theta1 * rsq;
    float4 h0, h1;
    h0.x = tpr * o0.x + tr * s0.x; h0.y = tpr * o0.y + tr * s0.y;
    h0.z = tpr * o0.z + tr * s0.z; h0.w = tpr * o0.w + tr * s0.w;
    h1.x = tpr * o1.x + tr * s1.x; h1.y = tpr * o1.y + tr * s1.y;
    h1.z = tpr * o1.z + tr * s1.z; h1.w = tpr * o1.w + tr * s1.w;
    h4[i0] = h0;
    h4[i0 + 1] = h1;

    uint4 hp;
    hp.x = h2u(__floats2half2_rn(s0.x, s0.y));
    hp.y = h2u(__floats2half2_rn(s0.z, s0.w));
    hp.z = h2u(__floats2half2_rn(s1.x, s1.y));
    hp.w = h2u(__floats2half2_rn(s1.z, s1.w));
    g_halfB[n * 4 + c] = hp;
}

// iterations 2-4: fp16 gather, in-place fp32 state, h accumulate.
// sel: 1 -> in=halfA out=halfB, 0 -> in=halfB out=halfA.
// last: iter4 also restores the zero-state invariant (g_cnt, g_total).
__global__ void __launch_bounds__(256)
k_iter(float4* __restrict__ h4, float theta, int write_next, int sel, int last) {
    const uint4* __restrict__ gin  = sel ? g_halfA : g_halfB;
    uint4* __restrict__       gout = sel ? g_halfB : g_halfA;

    int t = threadIdx.x;
    int n = blockIdx.x * 64 + (t >> 2);
    if (n >= N_NODES) return;
    int c = t & 3;

    int2 rr = g_rows[n];

    float a0 = 0.f, a1 = 0.f, a2 = 0.f, a3 = 0.f;
    float a4 = 0.f, a5 = 0.f, a6 = 0.f, a7 = 0.f;

    #pragma unroll 8
    for (int j = rr.x; j < rr.y; ++j) {
        int2 ed = g_edges[j];
        float m = __int_as_float(ed.y);
        uint4 v = gin[ed.x * 4 + c];
        float2 f;
        f = __half22float2(*reinterpret_cast<__half2*>(&v.x)); a0 += f.x * m; a1 += f.y * m;
        f = __half22float2(*reinterpret_cast<__half2*>(&v.y)); a2 += f.x * m; a3 += f.y * m;
        f = __half22float2(*reinterpret_cast<__half2*>(&v.z)); a4 += f.x * m; a5 += f.y * m;
        f = __half22float2(*reinterpret_cast<__half2*>(&v.w)); a6 += f.x * m; a7 += f.y * m;
    }

    float2 fac = g_fac[n];
    float dinv2 = fac.x, rsq = fac.y;

    int i0 = n * DV4 + c * 2;
    float4 s0 = g_scaled[i0], s1 = g_scaled[i0 + 1];
    s0.x -= a0 * dinv2; s0.y -= a1 * dinv2; s0.z -= a2 * dinv2; s0.w -= a3 * dinv2;
    s1.x -= a4 * dinv2; s1.y -= a5 * dinv2; s1.z -= a6 * dinv2; s1.w -= a7 * dinv2;
    g_scaled[i0] = s0;
    g_scaled[i0 + 1] = s1;

    float tr = theta * rsq;
    float4 h0 = h4[i0], h1 = h4[i0 + 1];
    h0.x += tr * s0.x; h0.y += tr * s0.y; h0.z += tr * s0.z; h0.w += tr * s0.w;
    h1.x += tr * s1.x; h1.y += tr * s1.y; h1.z += tr * s1.z; h1.w += tr * s1.w;
    h4[i0] = h0;
    h4[i0 + 1] = h1;

    if (write_next) {
        uint4 hp;
        hp.x = h2u(__floats2half2_rn(s0.x, s0.y));
        hp.y = h2u(__floats2half2_rn(s0.z, s0.w));
        hp.z = h2u(__floats2half2_rn(s1.x, s1.y));
        hp.w = h2u(__floats2half2_rn(s1.z, s1.w));
        gout[n * 4 + c] = hp;
    }

    if (last) {
        // restore zero-state invariant for the next call/replay
        if (c == 0) g_cnt[n] = 0;
        if (n == 0 && c == 0) g_total = 0;
    }
}

extern "C" void kernel_launch(void* const* d_in, const int* in_sizes, int n_in,
                              void* d_out, int out_size) {
    const float* feat = (const float*)d_in[0];
    const int*   src  = (const int*)d_in[1];
    const int*   dst  = (const int*)d_in[2];
    const float* mask = (const float*)d_in[3];
    float* out = (float*)d_out;

    const int E = in_sizes[1];
    const int TB = 256;

    // --- CSR build (no scan; atomic segment allocation) ---
    k_hist<<<(E + TB - 1) / TB, TB>>>(dst, E);
    k_rows<<<(N_NODES + TB - 1) / TB, TB>>>();
    k_scatter<<<(E + TB - 1) / TB, TB>>>(src, dst, mask, E);

    // --- factors + init (fused) ---
    int node4_blocks = (N_NODES + 63) / 64;
    k_facinit<<<node4_blocks, TB>>>((const float4*)feat);

    // --- 4 fused iterations ---  theta = {0.2, -0.4, 0.3, -0.15, 0.05}
    k_iter1<<<node4_blocks, TB>>>((float4*)out, 0.2f, -0.4f);
    k_iter<<<node4_blocks, TB>>>((float4*)out, 0.3f,   1, 0, 0);  // B -> A
    k_iter<<<node4_blocks, TB>>>((float4*)out, -0.15f, 1, 1, 0);  // A -> B
    k_iter<<<node4_blocks, TB>>>((float4*)out, 0.05f,  0, 0, 1);  // B, restore zeros
}